// round 5
// baseline (speedup 1.0000x reference)
#include <cuda_runtime.h>

#define NN 20000
#define EE 10000
#define IC 128
#define OC 64
#define BK2 32
#define SPLIT 16
#define BK3 32

// Scratch (no allocations allowed in kernel_launch)
__device__ float g_xt[NN * OC];      // x @ theta        [N, 64]
__device__ float g_edge[EE * OC];    // accumulators     [E, 64]
__device__ float g_de[EE];           // hyperedge degree [E]

// ---------------------------------------------------------------- zero
__global__ void zero_k() {
    int i = blockIdx.x * 256 + threadIdx.x;
    if (i < EE * OC) g_edge[i] = 0.0f;
    if (i < EE)      g_de[i]   = 0.0f;
}

// ---------------------------------------------------------------- xt = x @ theta
__global__ void xt_k(const float* __restrict__ x, const float* __restrict__ th) {
    __shared__ float ths[IC * OC];
    int tid = threadIdx.x;
    #pragma unroll
    for (int i = tid; i < IC * OC; i += 256) ths[i] = th[i];
    __syncthreads();

    int n = blockIdx.x * 4 + (tid >> 6);
    int c = tid & 63;
    const float* xr = x + (size_t)n * IC;
    float acc = 0.0f;
    #pragma unroll 8
    for (int k = 0; k < IC; ++k) acc += xr[k] * ths[k * OC + c];
    g_xt[n * OC + c] = acc;
}

// ---------------------------------------------------------------- pass2: edge_acc += H^T @ xt ; de += colsum(H)
// Split-K over N (SPLIT chunks of k-tiles), atomicAdd into g_edge/g_de.
__global__ void pass2_k(const float* __restrict__ H) {
    __shared__ float Hs[BK2][68];   // [k_local][e_local]
    __shared__ float Xs[BK2][68];   // [k_local][c]

    int tid = threadIdx.x;
    int e0  = blockIdx.x * 64;
    int tx  = tid & 15;             // channel group (4 ch)
    int ty  = tid >> 4;             // edge group (4 edges)

    const int TILES = NN / BK2;                 // 625
    const int TPC   = (TILES + SPLIT - 1) / SPLIT;
    int t0 = blockIdx.y * TPC;
    int t1 = t0 + TPC; if (t1 > TILES) t1 = TILES;

    bool full_e = (e0 + 64 <= EE);

    float acc[4][4];
    #pragma unroll
    for (int i = 0; i < 4; ++i)
        #pragma unroll
        for (int j = 0; j < 4; ++j) acc[i][j] = 0.0f;
    float dloc[4] = {0.0f, 0.0f, 0.0f, 0.0f};

    int lrow = tid >> 4;            // 0..15
    int lcol = tid & 15;            // float4 column

    for (int t = t0; t < t1; ++t) {
        int k0 = t * BK2;
        #pragma unroll
        for (int it = 0; it < 2; ++it) {
            int r = lrow + it * 16;
            // xt tile (always in-bounds: K exact multiple of 32, 64 channels)
            float4 xv = *(const float4*)&g_xt[(k0 + r) * OC + lcol * 4];
            *(float4*)&Xs[r][lcol * 4] = xv;
            // H tile
            int e = e0 + lcol * 4;
            float4 hv;
            if (full_e) {
                hv = *(const float4*)&H[(size_t)(k0 + r) * EE + e];
            } else {
                hv.x = (e + 0 < EE) ? H[(size_t)(k0 + r) * EE + e + 0] : 0.0f;
                hv.y = (e + 1 < EE) ? H[(size_t)(k0 + r) * EE + e + 1] : 0.0f;
                hv.z = (e + 2 < EE) ? H[(size_t)(k0 + r) * EE + e + 2] : 0.0f;
                hv.w = (e + 3 < EE) ? H[(size_t)(k0 + r) * EE + e + 3] : 0.0f;
            }
            *(float4*)&Hs[r][lcol * 4] = hv;
        }
        __syncthreads();

        #pragma unroll
        for (int kk = 0; kk < BK2; ++kk) {
            float a[4], b[4];
            *(float4*)a = *(const float4*)&Hs[kk][ty * 4];
            *(float4*)b = *(const float4*)&Xs[kk][tx * 4];
            #pragma unroll
            for (int i = 0; i < 4; ++i)
                #pragma unroll
                for (int j = 0; j < 4; ++j) acc[i][j] += a[i] * b[j];
            if (tx == 0) {
                #pragma unroll
                for (int i = 0; i < 4; ++i) dloc[i] += a[i];
            }
        }
        __syncthreads();
    }

    #pragma unroll
    for (int i = 0; i < 4; ++i) {
        int e = e0 + ty * 4 + i;
        if (e < EE) {
            #pragma unroll
            for (int j = 0; j < 4; ++j)
                atomicAdd(&g_edge[e * OC + tx * 4 + j], acc[i][j]);
            if (tx == 0) atomicAdd(&g_de[e], dloc[i]);
        }
    }
}

// ---------------------------------------------------------------- edge /= de
__global__ void div_k() {
    int i = blockIdx.x * 256 + threadIdx.x;
    if (i < EE * OC) g_edge[i] /= g_de[i >> 6];
}

// ---------------------------------------------------------------- pass3: out = (H @ edge) / rowsum(H)
__global__ void pass3_k(const float* __restrict__ H, float* __restrict__ out) {
    __shared__ float Ht[BK3][68];   // [k_local][n_local] (transposed)
    __shared__ float Es[BK3][68];   // [k_local][c]
    __shared__ float dn_s[64];

    int tid = threadIdx.x;
    int n0  = blockIdx.x * 64;
    int tx  = tid & 15;             // channel group
    int ty  = tid >> 4;             // node group

    float acc[4][4];
    #pragma unroll
    for (int i = 0; i < 4; ++i)
        #pragma unroll
        for (int j = 0; j < 4; ++j) acc[i][j] = 0.0f;
    float dloc[4] = {0.0f, 0.0f, 0.0f, 0.0f};

    const int KT = (EE + BK3 - 1) / BK3;        // 313

    for (int t = 0; t < KT; ++t) {
        int k0 = t * BK3;

        // Load H tile [64 nodes x 32 k] transposed into Ht[k][n]
        int lrow = tid >> 3;        // 0..31 (node offset per iter)
        int lcol = tid & 7;         // k float4 group
        #pragma unroll
        for (int it = 0; it < 2; ++it) {
            int nl = lrow + it * 32;
            int n  = n0 + nl;
            int kb = k0 + lcol * 4;
            float v[4];
            if (n < NN && kb + 4 <= EE) {
                float4 hv = *(const float4*)&H[(size_t)n * EE + kb];
                v[0] = hv.x; v[1] = hv.y; v[2] = hv.z; v[3] = hv.w;
            } else {
                #pragma unroll
                for (int j = 0; j < 4; ++j)
                    v[j] = (n < NN && kb + j < EE) ? H[(size_t)n * EE + kb + j] : 0.0f;
            }
            #pragma unroll
            for (int j = 0; j < 4; ++j) Ht[lcol * 4 + j][nl] = v[j];
        }

        // Load edge tile [32 k x 64 ch]
        #pragma unroll
        for (int it = 0; it < 2; ++it) {
            int kl = (tid >> 4) + it * 16;
            int k  = k0 + kl;
            float4 ev;
            if (k < EE) ev = *(const float4*)&g_edge[k * OC + (tid & 15) * 4];
            else        ev = make_float4(0.0f, 0.0f, 0.0f, 0.0f);
            *(float4*)&Es[kl][(tid & 15) * 4] = ev;
        }
        __syncthreads();

        #pragma unroll
        for (int kk = 0; kk < BK3; ++kk) {
            float a[4], b[4];
            *(float4*)a = *(const float4*)&Ht[kk][ty * 4];
            *(float4*)b = *(const float4*)&Es[kk][tx * 4];
            #pragma unroll
            for (int i = 0; i < 4; ++i)
                #pragma unroll
                for (int j = 0; j < 4; ++j) acc[i][j] += a[i] * b[j];
            if (tx == 0) {
                #pragma unroll
                for (int i = 0; i < 4; ++i) dloc[i] += a[i];
            }
        }
        __syncthreads();
    }

    if (tx == 0) {
        #pragma unroll
        for (int i = 0; i < 4; ++i) dn_s[ty * 4 + i] = dloc[i];
    }
    __syncthreads();

    #pragma unroll
    for (int i = 0; i < 4; ++i) {
        int n = n0 + ty * 4 + i;
        if (n < NN) {
            float inv = 1.0f / dn_s[ty * 4 + i];
            float4 o;
            o.x = acc[i][0] * inv;
            o.y = acc[i][1] * inv;
            o.z = acc[i][2] * inv;
            o.w = acc[i][3] * inv;
            *(float4*)&out[(size_t)n * OC + tx * 4] = o;
        }
    }
}

// ---------------------------------------------------------------- launch
extern "C" void kernel_launch(void* const* d_in, const int* in_sizes, int n_in,
                              void* d_out, int out_size) {
    const float* x  = (const float*)d_in[0];   // [N, 128]
    const float* H  = (const float*)d_in[1];   // [N, E]
    const float* th = (const float*)d_in[2];   // [128, 64]
    float* out = (float*)d_out;                // [N, 64]

    zero_k<<<(EE * OC + 255) / 256, 256>>>();
    xt_k<<<NN / 4, 256>>>(x, th);
    dim3 g2((EE + 63) / 64, SPLIT);
    pass2_k<<<g2, 256>>>(H);
    div_k<<<(EE * OC + 255) / 256, 256>>>();
    pass3_k<<<(NN + 63) / 64, 256>>>(H, out);
}

// round 7
// speedup vs baseline: 1.3096x; 1.3096x over previous
#include <cuda_runtime.h>
#include <cstdint>

#define NN 20000
#define EE 10000
#define IC 128
#define OC 64
#define SPLIT2 8

// Scratch (no allocations allowed)
__device__ float g_xt[NN * OC];
__device__ float g_edge[EE * OC];
__device__ float g_de[EE];

// ---------------------------------------------------------------- helpers
__device__ __forceinline__ uint32_t f2tf(float x) {
    uint32_t r;
    asm("cvt.rna.tf32.f32 %0, %1;" : "=r"(r) : "f"(x));
    return r;
}

__device__ __forceinline__ void mma8(float* c,
                                     uint32_t a0, uint32_t a1, uint32_t a2, uint32_t a3,
                                     uint32_t b0, uint32_t b1) {
    asm volatile(
        "mma.sync.aligned.m16n8k8.row.col.f32.tf32.tf32.f32 "
        "{%0,%1,%2,%3},{%4,%5,%6,%7},{%8,%9},{%0,%1,%2,%3};"
        : "+f"(c[0]), "+f"(c[1]), "+f"(c[2]), "+f"(c[3])
        : "r"(a0), "r"(a1), "r"(a2), "r"(a3), "r"(b0), "r"(b1));
}

// ---------------------------------------------------------------- zero
__global__ void zero_k() {
    int i = blockIdx.x * 256 + threadIdx.x;
    if (i < EE * OC) g_edge[i] = 0.0f;
    if (i < EE)      g_de[i]   = 0.0f;
}

// ---------------------------------------------------------------- xt = x @ theta
__global__ void xt_k(const float* __restrict__ x, const float* __restrict__ th) {
    __shared__ float ths[IC * OC];
    int tid = threadIdx.x;
    #pragma unroll
    for (int i = tid; i < IC * OC; i += 256) ths[i] = th[i];
    __syncthreads();

    int n = blockIdx.x * 4 + (tid >> 6);
    int c = tid & 63;
    const float* xr = x + (size_t)n * IC;
    float acc = 0.0f;
    #pragma unroll 8
    for (int k = 0; k < IC; ++k) acc += xr[k] * ths[k * OC + c];
    g_xt[n * OC + c] = acc;
}

// ---------------------------------------------------------------- pass2: edge += H^T @ xt ; de += colsum(H)
// C[E,64] tile 128x64 per block, K = N (split-K into SPLIT2 chunks, atomics).
__global__ __launch_bounds__(256, 2) void pass2_k(const float* __restrict__ H) {
    __shared__ float As[32][136];   // [k][e_local]  stride%32 == 8 -> conflict-free frags
    __shared__ float Bs[32][72];    // [k][c]
    __shared__ float dsm[8][128];

    int tid  = threadIdx.x;
    int lane = tid & 31, wid = tid >> 5;
    int e0   = blockIdx.x * 128;
    int wm   = wid >> 1, wn = wid & 1;
    int mo   = wm * 32,  no = wn * 32;
    int g    = lane >> 2, tg = lane & 3;

    const int TILES = NN / 32;                       // 625
    const int TPC   = (TILES + SPLIT2 - 1) / SPLIT2; // 79
    int t0 = blockIdx.y * TPC;
    int t1 = t0 + TPC; if (t1 > TILES) t1 = TILES;

    // A loader: thread -> k rows {wid, wid+8, wid+16, wid+24}, e = e0 + 4*lane
    int am = 4 * lane;
    bool eok = (e0 + am + 4 <= EE);                  // EE%4==0: float4 granularity
    // B loader: k = (tid>>4) + 16*it, c4 = 4*(tid&15)
    int bk = tid >> 4, bn = 4 * (tid & 15);

    float4 pa[4], pb[2];
    float dsum[4] = {0.f, 0.f, 0.f, 0.f};
    float c[2][4][4];
    #pragma unroll
    for (int mi = 0; mi < 2; ++mi)
        #pragma unroll
        for (int ni = 0; ni < 4; ++ni)
            #pragma unroll
            for (int j = 0; j < 4; ++j) c[mi][ni][j] = 0.f;

    // prefetch first tile
    {
        int t = t0;
        #pragma unroll
        for (int it = 0; it < 4; ++it) {
            int k = t * 32 + wid + 8 * it;
            pa[it] = eok ? *(const float4*)&H[(long)k * EE + e0 + am]
                         : make_float4(0.f, 0.f, 0.f, 0.f);
        }
        #pragma unroll
        for (int it = 0; it < 2; ++it)
            pb[it] = *(const float4*)&g_xt[(long)(t * 32 + bk + 16 * it) * OC + bn];
    }

    for (int t = t0; t < t1; ++t) {
        // stage current
        #pragma unroll
        for (int it = 0; it < 4; ++it) {
            *(float4*)&As[wid + 8 * it][am] = pa[it];
            dsum[0] += pa[it].x; dsum[1] += pa[it].y;
            dsum[2] += pa[it].z; dsum[3] += pa[it].w;
        }
        #pragma unroll
        for (int it = 0; it < 2; ++it)
            *(float4*)&Bs[bk + 16 * it][bn] = pb[it];
        __syncthreads();

        // prefetch next
        if (t + 1 < t1) {
            #pragma unroll
            for (int it = 0; it < 4; ++it) {
                int k = (t + 1) * 32 + wid + 8 * it;
                pa[it] = eok ? *(const float4*)&H[(long)k * EE + e0 + am]
                             : make_float4(0.f, 0.f, 0.f, 0.f);
            }
            #pragma unroll
            for (int it = 0; it < 2; ++it)
                pb[it] = *(const float4*)&g_xt[(long)((t + 1) * 32 + bk + 16 * it) * OC + bn];
        }

        // compute
        #pragma unroll
        for (int ko = 0; ko < 32; ko += 8) {
            uint32_t bh[4][2], bl[4][2];
            #pragma unroll
            for (int ni = 0; ni < 4; ++ni) {
                float v0 = Bs[ko + tg][no + ni * 8 + g];
                float v1 = Bs[ko + tg + 4][no + ni * 8 + g];
                bh[ni][0] = f2tf(v0); bl[ni][0] = f2tf(v0 - __uint_as_float(bh[ni][0]));
                bh[ni][1] = f2tf(v1); bl[ni][1] = f2tf(v1 - __uint_as_float(bh[ni][1]));
            }
            #pragma unroll
            for (int mi = 0; mi < 2; ++mi) {
                int mb = mo + mi * 16;
                float a0 = As[ko + tg][mb + g];
                float a1 = As[ko + tg][mb + g + 8];
                float a2 = As[ko + tg + 4][mb + g];
                float a3 = As[ko + tg + 4][mb + g + 8];
                uint32_t ah0 = f2tf(a0), ah1 = f2tf(a1), ah2 = f2tf(a2), ah3 = f2tf(a3);
                uint32_t al0 = f2tf(a0 - __uint_as_float(ah0));
                uint32_t al1 = f2tf(a1 - __uint_as_float(ah1));
                uint32_t al2 = f2tf(a2 - __uint_as_float(ah2));
                uint32_t al3 = f2tf(a3 - __uint_as_float(ah3));
                #pragma unroll
                for (int ni = 0; ni < 4; ++ni) {
                    mma8(c[mi][ni], ah0, ah1, ah2, ah3, bh[ni][0], bh[ni][1]);
                    mma8(c[mi][ni], ah0, ah1, ah2, ah3, bl[ni][0], bl[ni][1]);
                    mma8(c[mi][ni], al0, al1, al2, al3, bh[ni][0], bh[ni][1]);
                }
            }
        }
        __syncthreads();
    }

    // colsum reduction -> g_de
    #pragma unroll
    for (int j = 0; j < 4; ++j) dsm[wid][am + j] = dsum[j];
    __syncthreads();
    if (wid == 0) {
        float s[4] = {0.f, 0.f, 0.f, 0.f};
        #pragma unroll
        for (int w = 0; w < 8; ++w)
            #pragma unroll
            for (int j = 0; j < 4; ++j) s[j] += dsm[w][am + j];
        #pragma unroll
        for (int j = 0; j < 4; ++j) {
            int e = e0 + am + j;
            if (e < EE) atomicAdd(&g_de[e], s[j]);
        }
    }

    // accumulate edge tiles
    #pragma unroll
    for (int mi = 0; mi < 2; ++mi) {
        #pragma unroll
        for (int ni = 0; ni < 4; ++ni) {
            int er0 = e0 + mo + mi * 16 + g;
            int er1 = er0 + 8;
            int col = no + ni * 8 + 2 * tg;
            if (er0 < EE) {
                atomicAdd(&g_edge[er0 * OC + col],     c[mi][ni][0]);
                atomicAdd(&g_edge[er0 * OC + col + 1], c[mi][ni][1]);
            }
            if (er1 < EE) {
                atomicAdd(&g_edge[er1 * OC + col],     c[mi][ni][2]);
                atomicAdd(&g_edge[er1 * OC + col + 1], c[mi][ni][3]);
            }
        }
    }
}

// ---------------------------------------------------------------- edge /= de
__global__ void div_k() {
    int i = blockIdx.x * 256 + threadIdx.x;
    if (i < EE * OC) g_edge[i] /= g_de[i >> 6];
}

// ---------------------------------------------------------------- pass3: out = (H @ edge) / rowsum(H)
// C[N,64] tile 128x64 per block, K = E (full, no split).
__global__ __launch_bounds__(256, 2) void pass3_k(const float* __restrict__ H,
                                                  float* __restrict__ out) {
    __shared__ float As[128][36];   // [n_local][k]  stride%32 == 4 -> conflict-free frags
    __shared__ float Bs[32][72];    // [k][c]
    __shared__ float dn_s[128];

    int tid  = threadIdx.x;
    int lane = tid & 31, wid = tid >> 5;
    int n0   = blockIdx.x * 128;
    int wm   = wid >> 1, wn = wid & 1;
    int mo   = wm * 32,  no = wn * 32;
    int g    = lane >> 2, tg = lane & 3;

    // A loader: thread -> row = tid>>1, covers 16 k (4 float4) at cols s*16..
    int row = tid >> 1, s = tid & 1;
    int gn  = n0 + row;
    bool rok = (gn < NN);
    // B loader
    int bk = tid >> 4, bn = 4 * (tid & 15);

    float4 pa[4], pb[2];
    float rsum = 0.f;
    float c[2][4][4];
    #pragma unroll
    for (int mi = 0; mi < 2; ++mi)
        #pragma unroll
        for (int ni = 0; ni < 4; ++ni)
            #pragma unroll
            for (int j = 0; j < 4; ++j) c[mi][ni][j] = 0.f;

    const int KT = (EE + 31) / 32;   // 313

    // prefetch first tile
    {
        #pragma unroll
        for (int i = 0; i < 4; ++i) {
            int k = (s * 4 + i) * 4;
            pa[i] = (rok && k + 4 <= EE) ? *(const float4*)&H[(long)gn * EE + k]
                                         : make_float4(0.f, 0.f, 0.f, 0.f);
        }
        #pragma unroll
        for (int it = 0; it < 2; ++it) {
            int k = bk + 16 * it;
            pb[it] = (k < EE) ? *(const float4*)&g_edge[(long)k * OC + bn]
                              : make_float4(0.f, 0.f, 0.f, 0.f);
        }
    }

    for (int t = 0; t < KT; ++t) {
        #pragma unroll
        for (int i = 0; i < 4; ++i) {
            *(float4*)&As[row][(s * 4 + i) * 4] = pa[i];
            rsum += pa[i].x + pa[i].y + pa[i].z + pa[i].w;
        }
        #pragma unroll
        for (int it = 0; it < 2; ++it)
            *(float4*)&Bs[bk + 16 * it][bn] = pb[it];
        __syncthreads();

        if (t + 1 < KT) {
            int k0 = (t + 1) * 32;
            #pragma unroll
            for (int i = 0; i < 4; ++i) {
                int k = k0 + (s * 4 + i) * 4;
                pa[i] = (rok && k + 4 <= EE) ? *(const float4*)&H[(long)gn * EE + k]
                                             : make_float4(0.f, 0.f, 0.f, 0.f);
            }
            #pragma unroll
            for (int it = 0; it < 2; ++it) {
                int k = k0 + bk + 16 * it;
                pb[it] = (k < EE) ? *(const float4*)&g_edge[(long)k * OC + bn]
                                  : make_float4(0.f, 0.f, 0.f, 0.f);
            }
        }

        #pragma unroll
        for (int ko = 0; ko < 32; ko += 8) {
            uint32_t bh[4][2], bl[4][2];
            #pragma unroll
            for (int ni = 0; ni < 4; ++ni) {
                float v0 = Bs[ko + tg][no + ni * 8 + g];
                float v1 = Bs[ko + tg + 4][no + ni * 8 + g];
                bh[ni][0] = f2tf(v0); bl[ni][0] = f2tf(v0 - __uint_as_float(bh[ni][0]));
                bh[ni][1] = f2tf(v1); bl[ni][1] = f2tf(v1 - __uint_as_float(bh[ni][1]));
            }
            #pragma unroll
            for (int mi = 0; mi < 2; ++mi) {
                int mb = mo + mi * 16;
                float a0 = As[mb + g][ko + tg];
                float a1 = As[mb + g + 8][ko + tg];
                float a2 = As[mb + g][ko + tg + 4];
                float a3 = As[mb + g + 8][ko + tg + 4];
                uint32_t ah0 = f2tf(a0), ah1 = f2tf(a1), ah2 = f2tf(a2), ah3 = f2tf(a3);
                uint32_t al0 = f2tf(a0 - __uint_as_float(ah0));
                uint32_t al1 = f2tf(a1 - __uint_as_float(ah1));
                uint32_t al2 = f2tf(a2 - __uint_as_float(ah2));
                uint32_t al3 = f2tf(a3 - __uint_as_float(ah3));
                #pragma unroll
                for (int ni = 0; ni < 4; ++ni) {
                    mma8(c[mi][ni], ah0, ah1, ah2, ah3, bh[ni][0], bh[ni][1]);
                    mma8(c[mi][ni], ah0, ah1, ah2, ah3, bl[ni][0], bl[ni][1]);
                    mma8(c[mi][ni], al0, al1, al2, al3, bh[ni][0], bh[ni][1]);
                }
            }
        }
        __syncthreads();
    }

    // row degree: reduce pair (s=0,1) then stash
    float tot = rsum + __shfl_xor_sync(0xffffffffu, rsum, 1);
    if (s == 0) dn_s[row] = tot;
    __syncthreads();

    #pragma unroll
    for (int mi = 0; mi < 2; ++mi) {
        #pragma unroll
        for (int ni = 0; ni < 4; ++ni) {
            int r0  = mo + mi * 16 + g;
            int r1  = r0 + 8;
            int col = no + ni * 8 + 2 * tg;
            if (n0 + r0 < NN) {
                float inv = 1.0f / dn_s[r0];
                out[(long)(n0 + r0) * OC + col]     = c[mi][ni][0] * inv;
                out[(long)(n0 + r0) * OC + col + 1] = c[mi][ni][1] * inv;
            }
            if (n0 + r1 < NN) {
                float inv = 1.0f / dn_s[r1];
                out[(long)(n0 + r1) * OC + col]     = c[mi][ni][2] * inv;
                out[(long)(n0 + r1) * OC + col + 1] = c[mi][ni][3] * inv;
            }
        }
    }
}

// ---------------------------------------------------------------- launch
extern "C" void kernel_launch(void* const* d_in, const int* in_sizes, int n_in,
                              void* d_out, int out_size) {
    const float* x  = (const float*)d_in[0];   // [N, 128]
    const float* H  = (const float*)d_in[1];   // [N, E]
    const float* th = (const float*)d_in[2];   // [128, 64]
    float* out = (float*)d_out;                // [N, 64]

    zero_k<<<(EE * OC + 255) / 256, 256>>>();
    xt_k<<<NN / 4, 256>>>(x, th);
    dim3 g2((EE + 127) / 128, SPLIT2);
    pass2_k<<<g2, 256>>>(H);
    div_k<<<(EE * OC + 255) / 256, 256>>>();
    pass3_k<<<(NN + 127) / 128, 256>>>(H, out);
}